// round 14
// baseline (speedup 1.0000x reference)
#include <cuda_runtime.h>
#include <cuda_bf16.h>
#include <cstdint>

// ---------------------------------------------------------------------------
// RSSM observe scan, GB300 — round 14.
//   k_pre  : merged obs+inp split-bf16 mma GEMMs, now DOUBLE-BUFFERED
//            (2-stage smem pipeline, 1 barrier/chunk, loads overlap MMA).
//   k_rssm : bit-identical to R13 (best scan, mbarrier exchange).
// ---------------------------------------------------------------------------

#define Bc 512
#define Tc 64
#define Ec 1024
#define Ac 32
#define Sc 30
#define Dc 200
#define Hc 200
#define SSc 230
#define OUTC 380

typedef unsigned long long ull;

__device__ float g_pre_inp[Tc * Bc * Hc];
__device__ float g_pre_obs[Tc * Bc * Hc];

// ---- packed f32x2 helpers -------------------------------------------------
__device__ __forceinline__ ull pk2(float a, float b) {
    ull r; asm("mov.b64 %0, {%1, %2};" : "=l"(r) : "f"(a), "f"(b)); return r;
}
__device__ __forceinline__ ull dup2(float a) {
    ull r; asm("mov.b64 %0, {%1, %1};" : "=l"(r) : "f"(a)); return r;
}
__device__ __forceinline__ float2 up2(ull v) {
    float x, y; asm("mov.b64 {%0, %1}, %2;" : "=f"(x), "=f"(y) : "l"(v));
    return make_float2(x, y);
}
__device__ __forceinline__ void fma2(ull& acc, ull a, ull b) {
    asm("fma.rn.f32x2 %0, %1, %2, %0;" : "+l"(acc) : "l"(a), "l"(b));
}

__device__ __forceinline__ float sigm(float x) { return 1.0f / (1.0f + __expf(-x)); }
__device__ __forceinline__ float eluf(float x) { return x > 0.0f ? x : (__expf(x) - 1.0f); }
__device__ __forceinline__ float softplusf(float x) {
    return x > 15.0f ? x : log1pf(__expf(x));
}

// ---- cluster / smem helpers -------------------------------------------------
__device__ __forceinline__ uint32_t smem_u32(const void* p) {
    uint32_t a;
    asm("{ .reg .u64 t; cvta.to.shared.u64 t, %1; cvt.u32.u64 %0, t; }"
        : "=r"(a) : "l"(p));
    return a;
}
__device__ __forceinline__ void st_peer_u64(uint32_t laddr, uint32_t rank, ull v) {
    uint32_t ra;
    asm volatile("mapa.shared::cluster.u32 %0, %1, %2;" : "=r"(ra)
                 : "r"(laddr), "r"(rank));
    asm volatile("st.shared::cluster.u64 [%0], %1;" :: "r"(ra), "l"(v) : "memory");
}
__device__ __forceinline__ void st_peer_f32(uint32_t laddr, uint32_t rank, float v) {
    uint32_t ra;
    asm volatile("mapa.shared::cluster.u32 %0, %1, %2;" : "=r"(ra)
                 : "r"(laddr), "r"(rank));
    asm volatile("st.shared::cluster.f32 [%0], %1;" :: "r"(ra), "f"(v) : "memory");
}
__device__ __forceinline__ uint32_t ctarank() {
    uint32_t r; asm("mov.u32 %0, %%cluster_ctarank;" : "=r"(r)); return r;
}
__device__ __forceinline__ void mbar_init(uint32_t addr, uint32_t cnt) {
    asm volatile("mbarrier.init.shared.b64 [%0], %1;" :: "r"(addr), "r"(cnt)
                 : "memory");
}
__device__ __forceinline__ void mbar_arrive_peer(uint32_t laddr, uint32_t rank) {
    uint32_t ra;
    asm volatile("mapa.shared::cluster.u32 %0, %1, %2;" : "=r"(ra)
                 : "r"(laddr), "r"(rank));
    asm volatile("mbarrier.arrive.release.cluster.shared::cluster.b64 _, [%0];"
                 :: "r"(ra) : "memory");
}
__device__ __forceinline__ void mbar_wait(uint32_t addr, uint32_t parity) {
    asm volatile(
        "{\n\t.reg .pred P;\n\t"
        "W%=:\n\t"
        "mbarrier.try_wait.parity.acquire.cluster.shared::cta.b64 P, [%0], %1, 0x989680;\n\t"
        "@P bra D%=;\n\t"
        "bra W%=;\n\t"
        "D%=:\n\t}"
        :: "r"(addr), "r"(parity) : "memory");
}
#define CB() do { asm volatile("barrier.cluster.arrive.aligned;" ::: "memory"); \
                  asm volatile("barrier.cluster.wait.aligned;" ::: "memory"); } while (0)

// ---- mma.sync helpers (compute_103-legal) -----------------------------------
__device__ __forceinline__ void ldmx4(uint32_t* a, uint32_t addr) {
    asm volatile("ldmatrix.sync.aligned.m8n8.x4.shared.b16 {%0,%1,%2,%3}, [%4];"
                 : "=r"(a[0]), "=r"(a[1]), "=r"(a[2]), "=r"(a[3]) : "r"(addr));
}
__device__ __forceinline__ void ldmx2(uint32_t* a, uint32_t addr) {
    asm volatile("ldmatrix.sync.aligned.m8n8.x2.shared.b16 {%0,%1}, [%2];"
                 : "=r"(a[0]), "=r"(a[1]) : "r"(addr));
}
__device__ __forceinline__ void mma16816(float* c, const uint32_t* a,
                                         const uint32_t* b) {
    asm volatile(
        "mma.sync.aligned.m16n8k16.row.col.f32.bf16.bf16.f32 "
        "{%0,%1,%2,%3},{%4,%5,%6,%7},{%8,%9},{%0,%1,%2,%3};"
        : "+f"(c[0]), "+f"(c[1]), "+f"(c[2]), "+f"(c[3])
        : "r"(a[0]), "r"(a[1]), "r"(a[2]), "r"(a[3]), "r"(b[0]), "r"(b[1]));
}

// ===========================================================================
// k_pre: merged pre GEMMs, double-buffered.
// blocks [0,256): pre_obs (K=1024, 64 chunks); [256,512): pre_inp (17 chunks).
// Dynamic smem layout (bytes):
//   A buf (st,h): (st*2+h)*6144         4 bufs -> 24576
//   B buf (st,h): 24576 + (st*2+h)*9600 4 bufs -> 62976
//   bias        : 62976 (800)           total 63776
// ===========================================================================
#define PA_OFF(st, h) (((st) * 2 + (h)) * 6144)
#define PB_OFF(st, h) (24576 + ((st) * 2 + (h)) * 9600)
#define PBIAS_OFF 62976
#define KPRE_SMEM 63776

__global__ void __launch_bounds__(512, 1)
k_pre(const float* __restrict__ embed,
      const float* __restrict__ ctx,
      const float* __restrict__ actn,
      const float* __restrict__ w_obs,
      const float* __restrict__ b_obs,
      const float* __restrict__ w_inp,
      const float* __restrict__ b_inp) {
    extern __shared__ __align__(16) char dsm[];
    float* sbias = reinterpret_cast<float*>(dsm + PBIAS_OFF);

    const int tid = threadIdx.x;
    const int wid = tid >> 5, lane = tid & 31;
    const bool is_obs = blockIdx.x < 256;
    const int row0 = (is_obs ? blockIdx.x : blockIdx.x - 256) * 128;

    const int ar = tid >> 2;
    const int akq = (tid & 3) * 4;
    const int arg = row0 + ar;
    const int bb = arg & 511, tt = arg >> 9;
    int bk[7], bn[7];
#pragma unroll
    for (int j = 0; j < 7; j++) {
        int idx = tid + j * 512;
        bk[j] = idx / 200; bn[j] = idx - bk[j] * 200;
    }

    for (int i = tid; i < Hc; i += 512) sbias[i] = is_obs ? b_obs[i] : b_inp[i];

    const int mtile = wid >> 1;
    const int ntb = (wid & 1) * 13;
    const int ncnt = (wid & 1) ? 12 : 13;
    const uint32_t sb32 = smem_u32(dsm);
    const uint32_t aoff =
        (uint32_t)(((mtile * 16 + (lane & 15)) * 24 + (lane >> 4) * 8) * 2);
    const uint32_t boff =
        (uint32_t)((((lane & 7)) * 24 + ((lane >> 3) & 1) * 8) * 2) +
        (uint32_t)(ntb * 384);
    uint32_t aHi[2], aLo[2], bHi[2], bLo[2];
#pragma unroll
    for (int st = 0; st < 2; st++) {
        aHi[st] = sb32 + PA_OFF(st, 0) + aoff;
        aLo[st] = sb32 + PA_OFF(st, 1) + aoff;
        bHi[st] = sb32 + PB_OFF(st, 0) + boff;
        bLo[st] = sb32 + PB_OFF(st, 1) + boff;
    }

    float acc[13][4];
#pragma unroll
    for (int q = 0; q < 13; q++)
#pragma unroll
        for (int i = 0; i < 4; i++) acc[q][i] = 0.0f;

    const float* aSrcObs = embed + ((size_t)(bb * Tc + tt)) * Ec + akq;
    const float* ctxRow = ctx + (size_t)(bb * Tc + tt) * SSc;
    const float* actRow = actn + (size_t)(bb * Tc + tt) * Ac;
    const int nck = is_obs ? 64 : 17;

    float araw[4], braw[7];

    // ---- load chunk k0 into regs ----
    auto load_regs = [&](int k0) {
        if (is_obs) {
            float4 v = *reinterpret_cast<const float4*>(aSrcObs + k0);
            araw[0] = v.x; araw[1] = v.y; araw[2] = v.z; araw[3] = v.w;
#pragma unroll
            for (int j = 0; j < 7; j++)
                if (tid + j * 512 < 3200)
                    braw[j] = w_obs[(size_t)(Dc + k0 + bk[j]) * Hc + bn[j]];
        } else {
#pragma unroll
            for (int i = 0; i < 4; i++) {
                int kg = k0 + akq + i;
                araw[i] = (kg < SSc) ? ctxRow[kg]
                         : (kg < SSc + Ac ? actRow[kg - SSc] : 0.0f);
            }
#pragma unroll
            for (int j = 0; j < 7; j++) {
                if (tid + j * 512 < 3200) {
                    int kg = k0 + bk[j];
                    braw[j] = (kg < SSc + Ac)
                                  ? w_inp[(size_t)(Sc + kg) * Hc + bn[j]]
                                  : 0.0f;
                }
            }
        }
    };

    // ---- cvt regs -> smem stage st ----
    auto cvt_store = [&](int st) {
        __nv_bfloat16* ah =
            reinterpret_cast<__nv_bfloat16*>(dsm + PA_OFF(st, 0)) + ar * 24 + akq;
        __nv_bfloat16* al =
            reinterpret_cast<__nv_bfloat16*>(dsm + PA_OFF(st, 1)) + ar * 24 + akq;
#pragma unroll
        for (int i = 0; i < 4; i++) {
            __nv_bfloat16 h = __float2bfloat16(araw[i]);
            ah[i] = h;
            al[i] = __float2bfloat16(araw[i] - __bfloat162float(h));
        }
        __nv_bfloat16* bh = reinterpret_cast<__nv_bfloat16*>(dsm + PB_OFF(st, 0));
        __nv_bfloat16* bl = reinterpret_cast<__nv_bfloat16*>(dsm + PB_OFF(st, 1));
#pragma unroll
        for (int j = 0; j < 7; j++) {
            if (tid + j * 512 < 3200) {
                __nv_bfloat16 h = __float2bfloat16(braw[j]);
                bh[bn[j] * 24 + bk[j]] = h;
                bl[bn[j] * 24 + bk[j]] =
                    __float2bfloat16(braw[j] - __bfloat162float(h));
            }
        }
    };

    // prologue: chunk 0 -> stage 0
    load_regs(0);
    cvt_store(0);
    __syncthreads();

    for (int ck = 0; ck < nck; ck++) {
        const int st = ck & 1;
        const bool more = (ck + 1 < nck);
        if (more) load_regs((ck + 1) * 16);   // long-latency, overlaps MMA

        // ---- ldmatrix + mma on stage st ----
        {
            uint32_t ah[4], al[4];
            ldmx4(ah, aHi[st]);
            ldmx4(al, aLo[st]);
#pragma unroll
            for (int q = 0; q < 13; q++) {
                if (q < ncnt) {
                    uint32_t bh2[2], bl2[2];
                    ldmx2(bh2, bHi[st] + (uint32_t)q * 384);
                    ldmx2(bl2, bLo[st] + (uint32_t)q * 384);
                    mma16816(acc[q], ah, bh2);
                    mma16816(acc[q], al, bh2);
                    mma16816(acc[q], ah, bl2);
                }
            }
        }
        if (more) cvt_store(st ^ 1);          // stores to the OTHER stage
        __syncthreads();                       // one barrier per chunk
    }

    // ---- epilogue ----
    {
        float* gdst = is_obs ? g_pre_obs : g_pre_inp;
        const int gq = lane >> 2, t4 = lane & 3;
        const int m0 = row0 + mtile * 16 + gq;
#pragma unroll
        for (int q = 0; q < 13; q++) {
            if (q < ncnt) {
                const int n = (ntb + q) * 8 + 2 * t4;
                const float b0 = sbias[n], b1 = sbias[n + 1];
                *reinterpret_cast<float2*>(gdst + (size_t)m0 * Hc + n) =
                    make_float2(acc[q][0] + b0, acc[q][1] + b1);
                *reinterpret_cast<float2*>(gdst + (size_t)(m0 + 8) * Hc + n) =
                    make_float2(acc[q][2] + b0, acc[q][3] + b1);
            }
        }
    }
}

// ===========================================================================
// k_rssm — bit-identical to R13 (best scan)
// ===========================================================================
#define XD_OFF   0
#define DN_OFF   25600
#define HHO_OFF  38400
#define PART_OFF 64000
#define STS_OFF  104800
#define SOS_OFF  106848
#define STF_OFF  108896
#define BGRU_OFF 109920
#define BIMG_OFF 112320
#define BIMS_OFF 113120
#define BOBS_OFF 113376
#define MBAR_OFF 113632
#define SMEM_BYTES 113656

__global__ void __launch_bounds__(640, 1) __cluster_dims__(2, 1, 1) k_rssm(
    const float* __restrict__ noise_p, const float* __restrict__ noise_o,
    const float* __restrict__ w_inp,  const float* __restrict__ w_gru,
    const float* __restrict__ b_gru_g,
    const float* __restrict__ w_img,  const float* __restrict__ b_img_g,
    const float* __restrict__ w_obsd,
    const float* __restrict__ w_ims,  const float* __restrict__ b_ims_g,
    const float* __restrict__ w_obst, const float* __restrict__ b_obst_g,
    float* __restrict__ out) {
    extern __shared__ __align__(16) char sm[];
    ull*   xd_u   = reinterpret_cast<ull*>(sm + XD_OFF);
    ull*   dn_u   = reinterpret_cast<ull*>(sm + DN_OFF);
    ull*   hho_u  = reinterpret_cast<ull*>(sm + HHO_OFF);
    ull*   part_u = reinterpret_cast<ull*>(sm + PART_OFF);
    float* part_f = reinterpret_cast<float*>(sm + PART_OFF);
    float* stS    = reinterpret_cast<float*>(sm + STS_OFF);
    float* soS    = reinterpret_cast<float*>(sm + SOS_OFF);
    float* st_f   = reinterpret_cast<float*>(sm + STF_OFF);
    float* bgru   = reinterpret_cast<float*>(sm + BGRU_OFF);
    float* bimg   = reinterpret_cast<float*>(sm + BIMG_OFF);
    float* bims   = reinterpret_cast<float*>(sm + BIMS_OFF);
    float* bobs   = reinterpret_cast<float*>(sm + BOBS_OFF);
    const ulonglong2* xd_u2 = reinterpret_cast<const ulonglong2*>(xd_u);
    const ulonglong2* dn_u2 = reinterpret_cast<const ulonglong2*>(dn_u);
    const ulonglong2* hho_u2 = reinterpret_cast<const ulonglong2*>(hho_u);
    const float* xd_f = reinterpret_cast<const float*>(xd_u);
    const float* dn_f = reinterpret_cast<const float*>(dn_u);

    const int tid = threadIdx.x;
    const uint32_t p = ctarank();
    const uint32_t peer = 1u - p;
    const int b0 = (blockIdx.x >> 1) * 8;
    const uint32_t base32 = smem_u32(sm);
    const uint32_t mb_dn  = base32 + MBAR_OFF;
    const uint32_t mb_hho = base32 + MBAR_OFF + 8;
    const uint32_t mb_st  = base32 + MBAR_OFF + 16;

    for (int i = tid; i < 600; i += 640) bgru[i] = b_gru_g[i];
    for (int i = tid; i < Hc; i += 640) bimg[i] = b_img_g[i];
    if (tid < 60) { bims[tid] = b_ims_g[tid]; bobs[tid] = b_obst_g[tid]; }
    for (int i = tid; i < 1600; i += 640) xd_u[1600 + i] = 0ull;
    for (int i = tid; i < 256; i += 640) st_f[i] = 0.0f;
    if (tid == 0) {
        mbar_init(mb_dn, 400);
        mbar_init(mb_hho, 400);
        mbar_init(mb_st, 240);
    }
    __syncthreads();
    CB();

    uint32_t ph = 0;
    for (int t = 0; t < Tc; t++) {
        if (tid < 400) {
            const int j = tid >> 1, rh = tid & 1;
            const float* pi = g_pre_inp + ((size_t)t * Bc + b0) * Hc + j;
            float a0 = pi[(rh * 4 + 0) * Hc], a1 = pi[(rh * 4 + 1) * Hc];
            float a2 = pi[(rh * 4 + 2) * Hc], a3 = pi[(rh * 4 + 3) * Hc];
#pragma unroll
            for (int k = 0; k < Sc; k++) {
                float w = w_inp[k * Hc + j];
                float4 s = *reinterpret_cast<const float4*>(&st_f[k * 8 + rh * 4]);
                a0 = fmaf(w, s.x, a0); a1 = fmaf(w, s.y, a1);
                a2 = fmaf(w, s.z, a2); a3 = fmaf(w, s.w, a3);
            }
            ull* xo = &xd_u[j * 8 + rh * 4];
            xo[0] = dup2(eluf(a0)); xo[1] = dup2(eluf(a1));
            xo[2] = dup2(eluf(a2)); xo[3] = dup2(eluf(a3));
        }
        __syncthreads();

        if (tid < 600) {
            const int cg = tid % 75;
            const int z = tid / 75;
            const int rh = z & 1, seg = z >> 1;
            const int lc0 = cg * 4;
            const int gcol0 = (lc0 / 100) * 200 + (int)p * 100 + (lc0 % 100);
            const ulonglong2* Wp = reinterpret_cast<const ulonglong2*>(w_gru + gcol0)
                                   + (size_t)seg * 100 * 150;
            const ulonglong2* Ap = xd_u2 + (seg * 100) * 4 + rh * 2;
            ull A0 = 0, A1 = 0, A2 = 0, A3 = 0, A4 = 0, A5 = 0, A6 = 0, A7 = 0;
#pragma unroll 4
            for (int kk = 0; kk < 100; kk++) {
                ulonglong2 w = Wp[(size_t)kk * 150];
                ulonglong2 a01 = Ap[kk * 4];
                ulonglong2 a23 = Ap[kk * 4 + 1];
                fma2(A0, w.x, a01.x); fma2(A1, w.y, a01.x);
                fma2(A2, w.x, a01.y); fma2(A3, w.y, a01.y);
                fma2(A4, w.x, a23.x); fma2(A5, w.y, a23.x);
                fma2(A6, w.x, a23.y); fma2(A7, w.y, a23.y);
            }
            ull* P = part_u + (seg * 75 + cg) * 17 + rh * 4;
            P[0] = A0; P[8] = A1; P[1] = A2; P[9] = A3;
            P[2] = A4; P[10] = A5; P[3] = A6; P[11] = A7;
        }
        __syncthreads();

        if (tid < 400) {
            const int j = tid >> 2, q = tid & 3;
            const int gd = (int)p * 100 + j;
            const int jq = j >> 2, ci = j & 3, cp = ci >> 1, e = ci & 1;
            const float bR = bgru[gd], bC = bgru[200 + gd], bU = bgru[400 + gd];
#pragma unroll
            for (int w2 = 0; w2 < 2; w2++) {
                const int rr = q * 2 + w2;
                float R = bR, C = bC, U = bU - 1.0f;
#pragma unroll
                for (int seg = 0; seg < 4; seg++) {
                    R += part_f[(((seg * 75 + 0 * 25 + jq) * 17 + cp * 8 + rr) << 1) + e];
                    C += part_f[(((seg * 75 + 1 * 25 + jq) * 17 + cp * 8 + rr) << 1) + e];
                    U += part_f[(((seg * 75 + 2 * 25 + jq) * 17 + cp * 8 + rr) << 1) + e];
                }
                float reset = sigm(R);
                float cand  = tanhf(reset * C);
                float upd   = sigm(U);
                float dprev = xd_f[((200 + gd) * 8 + rr) * 2];
                float dnv = upd * cand + (1.0f - upd) * dprev;
                ull dv = dup2(dnv);
                dn_u[gd * 8 + rr] = dv;
                st_peer_u64(base32 + DN_OFF + (uint32_t)(gd * 8 + rr) * 8, peer, dv);
            }
            mbar_arrive_peer(mb_dn, peer);
        }
        __syncthreads();
        mbar_wait(mb_dn, ph);

        if (tid < 400) {
            const int grp = tid % 50;
            const int z = tid / 50;
            const int rh = z & 1, seg = z >> 1;
            const float* W = (grp < 25)
                ? (w_img + (int)p * 100 + grp * 4)
                : (w_obsd + (int)p * 100 + (grp - 25) * 4);
            const ulonglong2* Wp = reinterpret_cast<const ulonglong2*>(W)
                                   + (size_t)(seg * 50) * 50;
            const ulonglong2* Ap = dn_u2 + (seg * 50) * 4 + rh * 2;
            ull A0 = 0, A1 = 0, A2 = 0, A3 = 0, A4 = 0, A5 = 0, A6 = 0, A7 = 0;
#pragma unroll 5
            for (int kk = 0; kk < 50; kk++) {
                ulonglong2 w = Wp[(size_t)kk * 50];
                ulonglong2 a01 = Ap[kk * 4];
                ulonglong2 a23 = Ap[kk * 4 + 1];
                fma2(A0, w.x, a01.x); fma2(A1, w.y, a01.x);
                fma2(A2, w.x, a01.y); fma2(A3, w.y, a01.y);
                fma2(A4, w.x, a23.x); fma2(A5, w.y, a23.x);
                fma2(A6, w.x, a23.y); fma2(A7, w.y, a23.y);
            }
            ull* P = part_u + (seg * 50 + grp) * 17 + rh * 4;
            P[0] = A0; P[8] = A1; P[1] = A2; P[9] = A3;
            P[2] = A4; P[10] = A5; P[3] = A6; P[11] = A7;
        } else {
            const int tt2 = tid - 400;
            for (int i = tt2; i < 800; i += 240) {
                const int rl = i / 200, j = i % 200;
                const int r = (int)p * 4 + rl;
                out[((size_t)(b0 + r) * Tc + t) * OUTC + 180 + j] =
                    dn_f[(j * 8 + r) * 2];
            }
            for (int i = tt2; i < 1600; i += 240) xd_u[1600 + i] = dn_u[i];
        }
        __syncthreads();

        if (tid < 400) {
            const int cl = tid >> 1;
            const int rh = (tid & 1) * 4;
            const bool ish = cl < 100;
            const int gcol = (int)p * 100 + (ish ? cl : cl - 100);
            const int grp = ish ? (cl >> 2) : (25 + ((cl - 100) >> 2));
            const int ci = cl & 3, cp = ci >> 1, e = ci & 1;
            const float* po = g_pre_obs + ((size_t)t * Bc + b0) * Hc + gcol;
            const float bb = ish ? bimg[gcol] : 0.0f;
            const int dsti = ish ? gcol : 200 + gcol;
#pragma unroll
            for (int i = 0; i < 4; i++) {
                const int r = rh + i;
                float v = ish ? bb : po[r * Hc];
#pragma unroll
                for (int seg = 0; seg < 4; seg++)
                    v += part_f[(((seg * 50 + grp) * 17 + cp * 8 + r) << 1) + e];
                ull dv = dup2(eluf(v));
                hho_u[dsti * 8 + r] = dv;
                st_peer_u64(base32 + HHO_OFF + (uint32_t)(dsti * 8 + r) * 8, peer, dv);
            }
            mbar_arrive_peer(mb_hho, peer);
        }
        __syncthreads();
        mbar_wait(mb_hho, ph);

        if (tid < 240) {
            const int grp = tid % 15;
            const int z = tid / 15;
            const int rh = z & 1, seg = z >> 1;
            const float* W = (p ? w_obst : w_ims) + grp * 4;
            const ulonglong2* Wp = reinterpret_cast<const ulonglong2*>(W)
                                   + (size_t)(seg * 25) * 15;
            const ulonglong2* Ap = hho_u2 + (int)p * 800 + (seg * 25) * 4 + rh * 2;
            ull A0 = 0, A1 = 0, A2 = 0, A3 = 0, A4 = 0, A5 = 0, A6 = 0, A7 = 0;
#pragma unroll 5
            for (int kk = 0; kk < 25; kk++) {
                ulonglong2 w = Wp[(size_t)kk * 15];
                ulonglong2 a01 = Ap[kk * 4];
                ulonglong2 a23 = Ap[kk * 4 + 1];
                fma2(A0, w.x, a01.x); fma2(A1, w.y, a01.x);
                fma2(A2, w.x, a01.y); fma2(A3, w.y, a01.y);
                fma2(A4, w.x, a23.x); fma2(A5, w.y, a23.x);
                fma2(A6, w.x, a23.y); fma2(A7, w.y, a23.y);
            }
            ull* P = part_u + (seg * 15 + grp) * 17 + rh * 4;
            P[0] = A0; P[8] = A1; P[1] = A2; P[9] = A3;
            P[2] = A4; P[10] = A5; P[3] = A6; P[11] = A7;
        }
        __syncthreads();

        if (tid < 240) {
            const int col = tid >> 2, q = tid & 3;
            const int cgq = col >> 2, ci = col & 3, cp = ci >> 1, e = ci & 1;
            const float bb = p ? bobs[col] : bims[col];
            const uint32_t dstoff = p ? SOS_OFF : STS_OFF;
            float* dst = reinterpret_cast<float*>(sm + dstoff);
#pragma unroll
            for (int w2 = 0; w2 < 2; w2++) {
                const int rr = q * 2 + w2;
                float v = bb;
#pragma unroll
                for (int seg = 0; seg < 8; seg++)
                    v += part_f[(((seg * 15 + cgq) * 17 + cp * 8 + rr) << 1) + e];
                dst[rr * 64 + col] = v;
                st_peer_f32(base32 + dstoff + (uint32_t)(rr * 64 + col) * 4, peer, v);
            }
            mbar_arrive_peer(mb_st, peer);
        }
        __syncthreads();
        mbar_wait(mb_st, ph);

        if (tid < 240) {
            const int r = tid / 30, k = tid - r * 30;
            const int b = b0 + r;
            float om  = soS[r * 64 + k];
            float osv = softplusf(soS[r * 64 + 30 + k]) + 0.1f;
            float ost = fmaf(osv, noise_o[((size_t)t * Bc + b) * Sc + k], om);
            st_f[k * 8 + r] = ost;
            if ((r >> 2) == (int)p) {
                float pm  = stS[r * 64 + k];
                float psv = softplusf(stS[r * 64 + 30 + k]) + 0.1f;
                float pst = fmaf(psv, noise_p[((size_t)t * Bc + b) * Sc + k], pm);
                size_t basep = ((size_t)b * Tc + t) * OUTC;
                out[basep + k]       = om;
                out[basep + 30 + k]  = osv;
                out[basep + 60 + k]  = ost;
                out[basep + 90 + k]  = pm;
                out[basep + 120 + k] = psv;
                out[basep + 150 + k] = pst;
            }
        }
        __syncthreads();
        ph ^= 1;
    }
}

// ===========================================================================
extern "C" void kernel_launch(void* const* d_in, const int* in_sizes, int n_in,
                              void* d_out, int out_size) {
    const float* embed       = (const float*)d_in[0];
    const float* action      = (const float*)d_in[1];
    const float* context     = (const float*)d_in[2];
    const float* noise_prior = (const float*)d_in[3];
    const float* noise_post  = (const float*)d_in[4];
    const float* w_inp       = (const float*)d_in[5];
    const float* b_inp       = (const float*)d_in[6];
    const float* w_gru       = (const float*)d_in[7];
    const float* b_gru       = (const float*)d_in[8];
    const float* w_img_out   = (const float*)d_in[9];
    const float* b_img_out   = (const float*)d_in[10];
    const float* w_obs_out   = (const float*)d_in[11];
    const float* b_obs_out   = (const float*)d_in[12];
    const float* w_ims_stat  = (const float*)d_in[13];
    const float* b_ims_stat  = (const float*)d_in[14];
    const float* w_obs_stat  = (const float*)d_in[15];
    const float* b_obs_stat  = (const float*)d_in[16];
    float* out = (float*)d_out;

    static int smem_set = 0;
    if (!smem_set) {
        cudaFuncSetAttribute(k_rssm, cudaFuncAttributeMaxDynamicSharedMemorySize,
                             SMEM_BYTES);
        cudaFuncSetAttribute(k_pre, cudaFuncAttributeMaxDynamicSharedMemorySize,
                             KPRE_SMEM);
        smem_set = 1;
    }

    k_pre<<<512, 512, KPRE_SMEM>>>(embed, context, action, w_obs_out, b_obs_out,
                                   w_inp, b_inp);
    k_rssm<<<128, 640, SMEM_BYTES>>>(noise_prior, noise_post, w_inp, w_gru,
                                     b_gru, w_img_out, b_img_out, w_obs_out,
                                     w_ims_stat, b_ims_stat, w_obs_stat,
                                     b_obs_stat, out);
}

// round 17
// speedup vs baseline: 1.0019x; 1.0019x over previous
#include <cuda_runtime.h>
#include <cuda_bf16.h>
#include <cstdint>

// ---------------------------------------------------------------------------
// RSSM observe scan, GB300 — round 17.
//   Revert to the R13 proven configuration (best passing: 1889us).
//   Only change vs R13: deeper unroll in the scan's GRU (4->10) and P3
//   (5->10) weight loops to raise per-warp MLP. The GRU-mma line (R15/R16)
//   is abandoned after two identical-rel_err failures with disjoint load
//   machinery (latent shared bug).
// ---------------------------------------------------------------------------

#define Bc 512
#define Tc 64
#define Ec 1024
#define Ac 32
#define Sc 30
#define Dc 200
#define Hc 200
#define SSc 230
#define OUTC 380

typedef unsigned long long ull;

__device__ float g_pre_inp[Tc * Bc * Hc];
__device__ float g_pre_obs[Tc * Bc * Hc];

// ---- packed f32x2 helpers -------------------------------------------------
__device__ __forceinline__ ull pk2(float a, float b) {
    ull r; asm("mov.b64 %0, {%1, %2};" : "=l"(r) : "f"(a), "f"(b)); return r;
}
__device__ __forceinline__ ull dup2(float a) {
    ull r; asm("mov.b64 %0, {%1, %1};" : "=l"(r) : "f"(a)); return r;
}
__device__ __forceinline__ float2 up2(ull v) {
    float x, y; asm("mov.b64 {%0, %1}, %2;" : "=f"(x), "=f"(y) : "l"(v));
    return make_float2(x, y);
}
__device__ __forceinline__ void fma2(ull& acc, ull a, ull b) {
    asm("fma.rn.f32x2 %0, %1, %2, %0;" : "+l"(acc) : "l"(a), "l"(b));
}

__device__ __forceinline__ float sigm(float x) { return 1.0f / (1.0f + __expf(-x)); }
__device__ __forceinline__ float eluf(float x) { return x > 0.0f ? x : (__expf(x) - 1.0f); }
__device__ __forceinline__ float softplusf(float x) {
    return x > 15.0f ? x : log1pf(__expf(x));
}

// ---- cluster / smem helpers -------------------------------------------------
__device__ __forceinline__ uint32_t smem_u32(const void* p) {
    uint32_t a;
    asm("{ .reg .u64 t; cvta.to.shared.u64 t, %1; cvt.u32.u64 %0, t; }"
        : "=r"(a) : "l"(p));
    return a;
}
__device__ __forceinline__ void st_peer_u64(uint32_t laddr, uint32_t rank, ull v) {
    uint32_t ra;
    asm volatile("mapa.shared::cluster.u32 %0, %1, %2;" : "=r"(ra)
                 : "r"(laddr), "r"(rank));
    asm volatile("st.shared::cluster.u64 [%0], %1;" :: "r"(ra), "l"(v) : "memory");
}
__device__ __forceinline__ void st_peer_f32(uint32_t laddr, uint32_t rank, float v) {
    uint32_t ra;
    asm volatile("mapa.shared::cluster.u32 %0, %1, %2;" : "=r"(ra)
                 : "r"(laddr), "r"(rank));
    asm volatile("st.shared::cluster.f32 [%0], %1;" :: "r"(ra), "f"(v) : "memory");
}
__device__ __forceinline__ uint32_t ctarank() {
    uint32_t r; asm("mov.u32 %0, %%cluster_ctarank;" : "=r"(r)); return r;
}
__device__ __forceinline__ void mbar_init(uint32_t addr, uint32_t cnt) {
    asm volatile("mbarrier.init.shared.b64 [%0], %1;" :: "r"(addr), "r"(cnt)
                 : "memory");
}
__device__ __forceinline__ void mbar_arrive_peer(uint32_t laddr, uint32_t rank) {
    uint32_t ra;
    asm volatile("mapa.shared::cluster.u32 %0, %1, %2;" : "=r"(ra)
                 : "r"(laddr), "r"(rank));
    asm volatile("mbarrier.arrive.release.cluster.shared::cluster.b64 _, [%0];"
                 :: "r"(ra) : "memory");
}
__device__ __forceinline__ void mbar_wait(uint32_t addr, uint32_t parity) {
    asm volatile(
        "{\n\t.reg .pred P;\n\t"
        "W%=:\n\t"
        "mbarrier.try_wait.parity.acquire.cluster.shared::cta.b64 P, [%0], %1, 0x989680;\n\t"
        "@P bra D%=;\n\t"
        "bra W%=;\n\t"
        "D%=:\n\t}"
        :: "r"(addr), "r"(parity) : "memory");
}
#define CB() do { asm volatile("barrier.cluster.arrive.aligned;" ::: "memory"); \
                  asm volatile("barrier.cluster.wait.aligned;" ::: "memory"); } while (0)

// ---- mma.sync helpers (compute_103-legal) -----------------------------------
__device__ __forceinline__ void ldmx4(uint32_t* a, uint32_t addr) {
    asm volatile("ldmatrix.sync.aligned.m8n8.x4.shared.b16 {%0,%1,%2,%3}, [%4];"
                 : "=r"(a[0]), "=r"(a[1]), "=r"(a[2]), "=r"(a[3]) : "r"(addr));
}
__device__ __forceinline__ void ldmx2(uint32_t* a, uint32_t addr) {
    asm volatile("ldmatrix.sync.aligned.m8n8.x2.shared.b16 {%0,%1}, [%2];"
                 : "=r"(a[0]), "=r"(a[1]) : "r"(addr));
}
__device__ __forceinline__ void mma16816(float* c, const uint32_t* a,
                                         const uint32_t* b) {
    asm volatile(
        "mma.sync.aligned.m16n8k16.row.col.f32.bf16.bf16.f32 "
        "{%0,%1,%2,%3},{%4,%5,%6,%7},{%8,%9},{%0,%1,%2,%3};"
        : "+f"(c[0]), "+f"(c[1]), "+f"(c[2]), "+f"(c[3])
        : "r"(a[0]), "r"(a[1]), "r"(a[2]), "r"(a[3]), "r"(b[0]), "r"(b[1]));
}

// ===========================================================================
// k_pre: merged pre GEMMs (R13-proven). blocks [0,256): pre_obs (K=1024);
// [256,512): pre_inp (K=262 pad 272).
// ===========================================================================
__global__ void __launch_bounds__(512, 1)
k_pre(const float* __restrict__ embed,
      const float* __restrict__ ctx,
      const float* __restrict__ actn,
      const float* __restrict__ w_obs,
      const float* __restrict__ b_obs,
      const float* __restrict__ w_inp,
      const float* __restrict__ b_inp) {
    __shared__ __align__(16) __nv_bfloat16 sAhi[128 * 24];
    __shared__ __align__(16) __nv_bfloat16 sAlo[128 * 24];
    __shared__ __align__(16) __nv_bfloat16 sBhi[200 * 24];
    __shared__ __align__(16) __nv_bfloat16 sBlo[200 * 24];
    __shared__ float sbias[200];

    const int tid = threadIdx.x;
    const int wid = tid >> 5, lane = tid & 31;
    const bool is_obs = blockIdx.x < 256;
    const int row0 = (is_obs ? blockIdx.x : blockIdx.x - 256) * 128;

    const int ar = tid >> 2;
    const int akq = (tid & 3) * 4;
    const int arg = row0 + ar;
    const int bb = arg & 511, tt = arg >> 9;
    int bk[7], bn[7];
#pragma unroll
    for (int j = 0; j < 7; j++) {
        int idx = tid + j * 512;
        bk[j] = idx / 200; bn[j] = idx - bk[j] * 200;
    }

    for (int i = tid; i < Hc; i += 512) sbias[i] = is_obs ? b_obs[i] : b_inp[i];

    const int mtile = wid >> 1;
    const int ntb = (wid & 1) * 13;
    const int ncnt = (wid & 1) ? 12 : 13;
    const uint32_t aoff =
        (uint32_t)(((mtile * 16 + (lane & 15)) * 24 + (lane >> 4) * 8) * 2);
    const uint32_t aHiAddr = smem_u32(sAhi) + aoff;
    const uint32_t aLoAddr = smem_u32(sAlo) + aoff;
    const uint32_t boff =
        (uint32_t)((((lane & 7)) * 24 + ((lane >> 3) & 1) * 8) * 2);
    const uint32_t bHiBase = smem_u32(sBhi) + boff + (uint32_t)(ntb * 8 * 48);
    const uint32_t bLoBase = smem_u32(sBlo) + boff + (uint32_t)(ntb * 8 * 48);

    float acc[13][4];
#pragma unroll
    for (int q = 0; q < 13; q++)
#pragma unroll
        for (int i = 0; i < 4; i++) acc[q][i] = 0.0f;

    const float* aSrcObs = embed + ((size_t)(bb * Tc + tt)) * Ec + akq;
    const float* ctxRow = ctx + (size_t)(bb * Tc + tt) * SSc;
    const float* actRow = actn + (size_t)(bb * Tc + tt) * Ac;
    const int nck = is_obs ? 64 : 17;

    float araw[4], braw[7];
    if (is_obs) {
        float4 v = *reinterpret_cast<const float4*>(aSrcObs);
        araw[0] = v.x; araw[1] = v.y; araw[2] = v.z; araw[3] = v.w;
#pragma unroll
        for (int j = 0; j < 7; j++)
            if (tid + j * 512 < 3200)
                braw[j] = w_obs[(size_t)(Dc + bk[j]) * Hc + bn[j]];
    } else {
#pragma unroll
        for (int i = 0; i < 4; i++) {
            int kg = akq + i;
            araw[i] = (kg < SSc) ? ctxRow[kg]
                     : (kg < SSc + Ac ? actRow[kg - SSc] : 0.0f);
        }
#pragma unroll
        for (int j = 0; j < 7; j++) {
            if (tid + j * 512 < 3200) {
                int kg = bk[j];
                braw[j] = (kg < SSc + Ac) ? w_inp[(size_t)(Sc + kg) * Hc + bn[j]]
                                          : 0.0f;
            }
        }
    }

    for (int ck = 0; ck < nck; ck++) {
        {
            __nv_bfloat16* ah = sAhi + ar * 24 + akq;
            __nv_bfloat16* al = sAlo + ar * 24 + akq;
#pragma unroll
            for (int i = 0; i < 4; i++) {
                __nv_bfloat16 h = __float2bfloat16(araw[i]);
                ah[i] = h;
                al[i] = __float2bfloat16(araw[i] - __bfloat162float(h));
            }
#pragma unroll
            for (int j = 0; j < 7; j++) {
                if (tid + j * 512 < 3200) {
                    __nv_bfloat16 h = __float2bfloat16(braw[j]);
                    sBhi[bn[j] * 24 + bk[j]] = h;
                    sBlo[bn[j] * 24 + bk[j]] =
                        __float2bfloat16(braw[j] - __bfloat162float(h));
                }
            }
        }
        __syncthreads();

        if (ck + 1 < nck) {
            const int k0n = (ck + 1) * 16;
            if (is_obs) {
                float4 v = *reinterpret_cast<const float4*>(aSrcObs + k0n);
                araw[0] = v.x; araw[1] = v.y; araw[2] = v.z; araw[3] = v.w;
#pragma unroll
                for (int j = 0; j < 7; j++)
                    if (tid + j * 512 < 3200)
                        braw[j] = w_obs[(size_t)(Dc + k0n + bk[j]) * Hc + bn[j]];
            } else {
#pragma unroll
                for (int i = 0; i < 4; i++) {
                    int kg = k0n + akq + i;
                    araw[i] = (kg < SSc) ? ctxRow[kg]
                             : (kg < SSc + Ac ? actRow[kg - SSc] : 0.0f);
                }
#pragma unroll
                for (int j = 0; j < 7; j++) {
                    if (tid + j * 512 < 3200) {
                        int kg = k0n + bk[j];
                        braw[j] = (kg < SSc + Ac)
                                      ? w_inp[(size_t)(Sc + kg) * Hc + bn[j]]
                                      : 0.0f;
                    }
                }
            }
        }

        {
            uint32_t ah[4], al[4];
            ldmx4(ah, aHiAddr);
            ldmx4(al, aLoAddr);
#pragma unroll
            for (int q = 0; q < 13; q++) {
                if (q < ncnt) {
                    uint32_t bh2[2], bl2[2];
                    ldmx2(bh2, bHiBase + (uint32_t)q * 384);
                    ldmx2(bl2, bLoBase + (uint32_t)q * 384);
                    mma16816(acc[q], ah, bh2);
                    mma16816(acc[q], al, bh2);
                    mma16816(acc[q], ah, bl2);
                }
            }
        }
        __syncthreads();
    }

    {
        float* gdst = is_obs ? g_pre_obs : g_pre_inp;
        const int gq = lane >> 2, t4 = lane & 3;
        const int m0 = row0 + mtile * 16 + gq;
#pragma unroll
        for (int q = 0; q < 13; q++) {
            if (q < ncnt) {
                const int n = (ntb + q) * 8 + 2 * t4;
                const float b0 = sbias[n], b1 = sbias[n + 1];
                *reinterpret_cast<float2*>(gdst + (size_t)m0 * Hc + n) =
                    make_float2(acc[q][0] + b0, acc[q][1] + b1);
                *reinterpret_cast<float2*>(gdst + (size_t)(m0 + 8) * Hc + n) =
                    make_float2(acc[q][2] + b0, acc[q][3] + b1);
            }
        }
    }
}

// ===========================================================================
// k_rssm — exact R13 scan (mbarrier exchange), unrolls deepened (P2 10, P3 10)
// ===========================================================================
#define XD_OFF   0
#define DN_OFF   25600
#define HHO_OFF  38400
#define PART_OFF 64000
#define STS_OFF  104800
#define SOS_OFF  106848
#define STF_OFF  108896
#define BGRU_OFF 109920
#define BIMG_OFF 112320
#define BIMS_OFF 113120
#define BOBS_OFF 113376
#define MBAR_OFF 113632
#define SMEM_BYTES 113656

__global__ void __launch_bounds__(640, 1) __cluster_dims__(2, 1, 1) k_rssm(
    const float* __restrict__ noise_p, const float* __restrict__ noise_o,
    const float* __restrict__ w_inp,  const float* __restrict__ w_gru,
    const float* __restrict__ b_gru_g,
    const float* __restrict__ w_img,  const float* __restrict__ b_img_g,
    const float* __restrict__ w_obsd,
    const float* __restrict__ w_ims,  const float* __restrict__ b_ims_g,
    const float* __restrict__ w_obst, const float* __restrict__ b_obst_g,
    float* __restrict__ out) {
    extern __shared__ __align__(16) char sm[];
    ull*   xd_u   = reinterpret_cast<ull*>(sm + XD_OFF);
    ull*   dn_u   = reinterpret_cast<ull*>(sm + DN_OFF);
    ull*   hho_u  = reinterpret_cast<ull*>(sm + HHO_OFF);
    ull*   part_u = reinterpret_cast<ull*>(sm + PART_OFF);
    float* part_f = reinterpret_cast<float*>(sm + PART_OFF);
    float* stS    = reinterpret_cast<float*>(sm + STS_OFF);
    float* soS    = reinterpret_cast<float*>(sm + SOS_OFF);
    float* st_f   = reinterpret_cast<float*>(sm + STF_OFF);
    float* bgru   = reinterpret_cast<float*>(sm + BGRU_OFF);
    float* bimg   = reinterpret_cast<float*>(sm + BIMG_OFF);
    float* bims   = reinterpret_cast<float*>(sm + BIMS_OFF);
    float* bobs   = reinterpret_cast<float*>(sm + BOBS_OFF);
    const ulonglong2* xd_u2 = reinterpret_cast<const ulonglong2*>(xd_u);
    const ulonglong2* dn_u2 = reinterpret_cast<const ulonglong2*>(dn_u);
    const ulonglong2* hho_u2 = reinterpret_cast<const ulonglong2*>(hho_u);
    const float* xd_f = reinterpret_cast<const float*>(xd_u);
    const float* dn_f = reinterpret_cast<const float*>(dn_u);

    const int tid = threadIdx.x;
    const uint32_t p = ctarank();
    const uint32_t peer = 1u - p;
    const int b0 = (blockIdx.x >> 1) * 8;
    const uint32_t base32 = smem_u32(sm);
    const uint32_t mb_dn  = base32 + MBAR_OFF;
    const uint32_t mb_hho = base32 + MBAR_OFF + 8;
    const uint32_t mb_st  = base32 + MBAR_OFF + 16;

    for (int i = tid; i < 600; i += 640) bgru[i] = b_gru_g[i];
    for (int i = tid; i < Hc; i += 640) bimg[i] = b_img_g[i];
    if (tid < 60) { bims[tid] = b_ims_g[tid]; bobs[tid] = b_obst_g[tid]; }
    for (int i = tid; i < 1600; i += 640) xd_u[1600 + i] = 0ull;
    for (int i = tid; i < 256; i += 640) st_f[i] = 0.0f;
    if (tid == 0) {
        mbar_init(mb_dn, 400);
        mbar_init(mb_hho, 400);
        mbar_init(mb_st, 240);
    }
    __syncthreads();
    CB();

    uint32_t ph = 0;
    for (int t = 0; t < Tc; t++) {
        if (tid < 400) {
            const int j = tid >> 1, rh = tid & 1;
            const float* pi = g_pre_inp + ((size_t)t * Bc + b0) * Hc + j;
            float a0 = pi[(rh * 4 + 0) * Hc], a1 = pi[(rh * 4 + 1) * Hc];
            float a2 = pi[(rh * 4 + 2) * Hc], a3 = pi[(rh * 4 + 3) * Hc];
#pragma unroll
            for (int k = 0; k < Sc; k++) {
                float w = w_inp[k * Hc + j];
                float4 s = *reinterpret_cast<const float4*>(&st_f[k * 8 + rh * 4]);
                a0 = fmaf(w, s.x, a0); a1 = fmaf(w, s.y, a1);
                a2 = fmaf(w, s.z, a2); a3 = fmaf(w, s.w, a3);
            }
            ull* xo = &xd_u[j * 8 + rh * 4];
            xo[0] = dup2(eluf(a0)); xo[1] = dup2(eluf(a1));
            xo[2] = dup2(eluf(a2)); xo[3] = dup2(eluf(a3));
        }
        __syncthreads();

        if (tid < 600) {
            const int cg = tid % 75;
            const int z = tid / 75;
            const int rh = z & 1, seg = z >> 1;
            const int lc0 = cg * 4;
            const int gcol0 = (lc0 / 100) * 200 + (int)p * 100 + (lc0 % 100);
            const ulonglong2* Wp = reinterpret_cast<const ulonglong2*>(w_gru + gcol0)
                                   + (size_t)seg * 100 * 150;
            const ulonglong2* Ap = xd_u2 + (seg * 100) * 4 + rh * 2;
            ull A0 = 0, A1 = 0, A2 = 0, A3 = 0, A4 = 0, A5 = 0, A6 = 0, A7 = 0;
#pragma unroll 10
            for (int kk = 0; kk < 100; kk++) {
                ulonglong2 w = Wp[(size_t)kk * 150];
                ulonglong2 a01 = Ap[kk * 4];
                ulonglong2 a23 = Ap[kk * 4 + 1];
                fma2(A0, w.x, a01.x); fma2(A1, w.y, a01.x);
                fma2(A2, w.x, a01.y); fma2(A3, w.y, a01.y);
                fma2(A4, w.x, a23.x); fma2(A5, w.y, a23.x);
                fma2(A6, w.x, a23.y); fma2(A7, w.y, a23.y);
            }
            ull* P = part_u + (seg * 75 + cg) * 17 + rh * 4;
            P[0] = A0; P[8] = A1; P[1] = A2; P[9] = A3;
            P[2] = A4; P[10] = A5; P[3] = A6; P[11] = A7;
        }
        __syncthreads();

        if (tid < 400) {
            const int j = tid >> 2, q = tid & 3;
            const int gd = (int)p * 100 + j;
            const int jq = j >> 2, ci = j & 3, cp = ci >> 1, e = ci & 1;
            const float bR = bgru[gd], bC = bgru[200 + gd], bU = bgru[400 + gd];
#pragma unroll
            for (int w2 = 0; w2 < 2; w2++) {
                const int rr = q * 2 + w2;
                float R = bR, C = bC, U = bU - 1.0f;
#pragma unroll
                for (int seg = 0; seg < 4; seg++) {
                    R += part_f[(((seg * 75 + 0 * 25 + jq) * 17 + cp * 8 + rr) << 1) + e];
                    C += part_f[(((seg * 75 + 1 * 25 + jq) * 17 + cp * 8 + rr) << 1) + e];
                    U += part_f[(((seg * 75 + 2 * 25 + jq) * 17 + cp * 8 + rr) << 1) + e];
                }
                float reset = sigm(R);
                float cand  = tanhf(reset * C);
                float upd   = sigm(U);
                float dprev = xd_f[((200 + gd) * 8 + rr) * 2];
                float dnv = upd * cand + (1.0f - upd) * dprev;
                ull dv = dup2(dnv);
                dn_u[gd * 8 + rr] = dv;
                st_peer_u64(base32 + DN_OFF + (uint32_t)(gd * 8 + rr) * 8, peer, dv);
            }
            mbar_arrive_peer(mb_dn, peer);
        }
        __syncthreads();
        mbar_wait(mb_dn, ph);

        if (tid < 400) {
            const int grp = tid % 50;
            const int z = tid / 50;
            const int rh = z & 1, seg = z >> 1;
            const float* W = (grp < 25)
                ? (w_img + (int)p * 100 + grp * 4)
                : (w_obsd + (int)p * 100 + (grp - 25) * 4);
            const ulonglong2* Wp = reinterpret_cast<const ulonglong2*>(W)
                                   + (size_t)(seg * 50) * 50;
            const ulonglong2* Ap = dn_u2 + (seg * 50) * 4 + rh * 2;
            ull A0 = 0, A1 = 0, A2 = 0, A3 = 0, A4 = 0, A5 = 0, A6 = 0, A7 = 0;
#pragma unroll 10
            for (int kk = 0; kk < 50; kk++) {
                ulonglong2 w = Wp[(size_t)kk * 50];
                ulonglong2 a01 = Ap[kk * 4];
                ulonglong2 a23 = Ap[kk * 4 + 1];
                fma2(A0, w.x, a01.x); fma2(A1, w.y, a01.x);
                fma2(A2, w.x, a01.y); fma2(A3, w.y, a01.y);
                fma2(A4, w.x, a23.x); fma2(A5, w.y, a23.x);
                fma2(A6, w.x, a23.y); fma2(A7, w.y, a23.y);
            }
            ull* P = part_u + (seg * 50 + grp) * 17 + rh * 4;
            P[0] = A0; P[8] = A1; P[1] = A2; P[9] = A3;
            P[2] = A4; P[10] = A5; P[3] = A6; P[11] = A7;
        } else {
            const int tt2 = tid - 400;
            for (int i = tt2; i < 800; i += 240) {
                const int rl = i / 200, j = i % 200;
                const int r = (int)p * 4 + rl;
                out[((size_t)(b0 + r) * Tc + t) * OUTC + 180 + j] =
                    dn_f[(j * 8 + r) * 2];
            }
            for (int i = tt2; i < 1600; i += 240) xd_u[1600 + i] = dn_u[i];
        }
        __syncthreads();

        if (tid < 400) {
            const int cl = tid >> 1;
            const int rh = (tid & 1) * 4;
            const bool ish = cl < 100;
            const int gcol = (int)p * 100 + (ish ? cl : cl - 100);
            const int grp = ish ? (cl >> 2) : (25 + ((cl - 100) >> 2));
            const int ci = cl & 3, cp = ci >> 1, e = ci & 1;
            const float* po = g_pre_obs + ((size_t)t * Bc + b0) * Hc + gcol;
            const float bb = ish ? bimg[gcol] : 0.0f;
            const int dsti = ish ? gcol : 200 + gcol;
#pragma unroll
            for (int i = 0; i < 4; i++) {
                const int r = rh + i;
                float v = ish ? bb : po[r * Hc];
#pragma unroll
                for (int seg = 0; seg < 4; seg++)
                    v += part_f[(((seg * 50 + grp) * 17 + cp * 8 + r) << 1) + e];
                ull dv = dup2(eluf(v));
                hho_u[dsti * 8 + r] = dv;
                st_peer_u64(base32 + HHO_OFF + (uint32_t)(dsti * 8 + r) * 8, peer, dv);
            }
            mbar_arrive_peer(mb_hho, peer);
        }
        __syncthreads();
        mbar_wait(mb_hho, ph);

        if (tid < 240) {
            const int grp = tid % 15;
            const int z = tid / 15;
            const int rh = z & 1, seg = z >> 1;
            const float* W = (p ? w_obst : w_ims) + grp * 4;
            const ulonglong2* Wp = reinterpret_cast<const ulonglong2*>(W)
                                   + (size_t)(seg * 25) * 15;
            const ulonglong2* Ap = hho_u2 + (int)p * 800 + (seg * 25) * 4 + rh * 2;
            ull A0 = 0, A1 = 0, A2 = 0, A3 = 0, A4 = 0, A5 = 0, A6 = 0, A7 = 0;
#pragma unroll 5
            for (int kk = 0; kk < 25; kk++) {
                ulonglong2 w = Wp[(size_t)kk * 15];
                ulonglong2 a01 = Ap[kk * 4];
                ulonglong2 a23 = Ap[kk * 4 + 1];
                fma2(A0, w.x, a01.x); fma2(A1, w.y, a01.x);
                fma2(A2, w.x, a01.y); fma2(A3, w.y, a01.y);
                fma2(A4, w.x, a23.x); fma2(A5, w.y, a23.x);
                fma2(A6, w.x, a23.y); fma2(A7, w.y, a23.y);
            }
            ull* P = part_u + (seg * 15 + grp) * 17 + rh * 4;
            P[0] = A0; P[8] = A1; P[1] = A2; P[9] = A3;
            P[2] = A4; P[10] = A5; P[3] = A6; P[11] = A7;
        }
        __syncthreads();

        if (tid < 240) {
            const int col = tid >> 2, q = tid & 3;
            const int cgq = col >> 2, ci = col & 3, cp = ci >> 1, e = ci & 1;
            const float bb = p ? bobs[col] : bims[col];
            const uint32_t dstoff = p ? SOS_OFF : STS_OFF;
            float* dst = reinterpret_cast<float*>(sm + dstoff);
#pragma unroll
            for (int w2 = 0; w2 < 2; w2++) {
                const int rr = q * 2 + w2;
                float v = bb;
#pragma unroll
                for (int seg = 0; seg < 8; seg++)
                    v += part_f[(((seg * 15 + cgq) * 17 + cp * 8 + rr) << 1) + e];
                dst[rr * 64 + col] = v;
                st_peer_f32(base32 + dstoff + (uint32_t)(rr * 64 + col) * 4, peer, v);
            }
            mbar_arrive_peer(mb_st, peer);
        }
        __syncthreads();
        mbar_wait(mb_st, ph);

        if (tid < 240) {
            const int r = tid / 30, k = tid - r * 30;
            const int b = b0 + r;
            float om  = soS[r * 64 + k];
            float osv = softplusf(soS[r * 64 + 30 + k]) + 0.1f;
            float ost = fmaf(osv, noise_o[((size_t)t * Bc + b) * Sc + k], om);
            st_f[k * 8 + r] = ost;
            if ((r >> 2) == (int)p) {
                float pm  = stS[r * 64 + k];
                float psv = softplusf(stS[r * 64 + 30 + k]) + 0.1f;
                float pst = fmaf(psv, noise_p[((size_t)t * Bc + b) * Sc + k], pm);
                size_t basep = ((size_t)b * Tc + t) * OUTC;
                out[basep + k]       = om;
                out[basep + 30 + k]  = osv;
                out[basep + 60 + k]  = ost;
                out[basep + 90 + k]  = pm;
                out[basep + 120 + k] = psv;
                out[basep + 150 + k] = pst;
            }
        }
        __syncthreads();
        ph ^= 1;
    }
}

// ===========================================================================
extern "C" void kernel_launch(void* const* d_in, const int* in_sizes, int n_in,
                              void* d_out, int out_size) {
    const float* embed       = (const float*)d_in[0];
    const float* action      = (const float*)d_in[1];
    const float* context     = (const float*)d_in[2];
    const float* noise_prior = (const float*)d_in[3];
    const float* noise_post  = (const float*)d_in[4];
    const float* w_inp       = (const float*)d_in[5];
    const float* b_inp       = (const float*)d_in[6];
    const float* w_gru       = (const float*)d_in[7];
    const float* b_gru       = (const float*)d_in[8];
    const float* w_img_out   = (const float*)d_in[9];
    const float* b_img_out   = (const float*)d_in[10];
    const float* w_obs_out   = (const float*)d_in[11];
    const float* b_obs_out   = (const float*)d_in[12];
    const float* w_ims_stat  = (const float*)d_in[13];
    const float* b_ims_stat  = (const float*)d_in[14];
    const float* w_obs_stat  = (const float*)d_in[15];
    const float* b_obs_stat  = (const float*)d_in[16];
    float* out = (float*)d_out;

    static int smem_set = 0;
    if (!smem_set) {
        cudaFuncSetAttribute(k_rssm, cudaFuncAttributeMaxDynamicSharedMemorySize,
                             SMEM_BYTES);
        smem_set = 1;
    }

    k_pre<<<512, 512>>>(embed, context, action, w_obs_out, b_obs_out,
                        w_inp, b_inp);
    k_rssm<<<128, 640, SMEM_BYTES>>>(noise_prior, noise_post, w_inp, w_gru,
                                     b_gru, w_img_out, b_img_out, w_obs_out,
                                     w_ims_stat, b_ims_stat, w_obs_stat,
                                     b_obs_stat, out);
}